// round 1
// baseline (speedup 1.0000x reference)
#include <cuda_runtime.h>
#include <math.h>
#include <float.h>

#define B    32
#define HW   4096
#define D    256
#define NPQ  512
#define NQ   3
#define NPOS 10
#define NPAIR 30          // NQ * NPOS per batch

// ---- scratch (device globals; no allocation allowed) ----
__device__ float g_attn[B * NQ * HW];       // attention scores [b][q][hw]
__device__ int   g_topk[B * NQ * NPOS];     // selected hw indices, descending value
__device__ float g_part[B * NPAIR];         // per-pair partial loss sums
__device__ int   g_is64;                    // rand_idx dtype flag

// ---------------------------------------------------------------------------
// Detect whether rand_idx is int64 (jax x64) or int32.
// int64 nonneg values < 2^31 -> every odd 32-bit word is 0.
// For genuine int32 data (uniform in [0,4096)), P(all 48 odd words == 0) ~ 0.
// Reads only 96 words = 384 bytes, safe under both layouts.
// ---------------------------------------------------------------------------
__global__ void detect_idx_kernel(const int* __restrict__ r32) {
    if (threadIdx.x == 0) {
        int nz = 0;
        for (int i = 1; i < 2 * B * NQ; i += 2) nz += (r32[i] != 0);
        g_is64 = (nz == 0) ? 1 : 0;
    }
}

__device__ __forceinline__ int load_idx(const void* p, int i) {
    return g_is64 ? (int)((const long long*)p)[i] : ((const int*)p)[i];
}

// ---------------------------------------------------------------------------
// Kernel A: attn[b][q][r] = dot(z[b, rand_idx[b,q], :], z_pos[b, r, :])
// grid (B, 16 chunks of 256 rows), 256 threads (8 warps).
// Each warp handles one row per iteration: lane owns cols lane*8..lane*8+7,
// queries held in registers, warp-shuffle reduction. Unrolled x2 for MLP.
// Reads z_pos exactly once: 134 MB total -> HBM bound.
// ---------------------------------------------------------------------------
__global__ void __launch_bounds__(256) attn_kernel(
    const float* __restrict__ z,
    const float* __restrict__ z_pos,
    const void*  __restrict__ ridx)
{
    const int b     = blockIdx.x;
    const int chunk = blockIdx.y;
    const int tid   = threadIdx.x;
    const int w     = tid >> 5;
    const int lane  = tid & 31;

    __shared__ int qrow[NQ];
    if (tid < NQ) qrow[tid] = load_idx(ridx, b * NQ + tid);
    __syncthreads();

    // Per-lane query registers: columns [lane*8, lane*8+8)
    const float* zb = z + (size_t)b * HW * D;
    float q[NQ][8];
#pragma unroll
    for (int s = 0; s < NQ; s++) {
        const float4* qp = (const float4*)(zb + (size_t)qrow[s] * D + lane * 8);
        float4 a = qp[0], c = qp[1];
        q[s][0] = a.x; q[s][1] = a.y; q[s][2] = a.z; q[s][3] = a.w;
        q[s][4] = c.x; q[s][5] = c.y; q[s][6] = c.z; q[s][7] = c.w;
    }

    const float* zpb   = z_pos + (size_t)b * HW * D;
    const int    rbase = chunk * 256;

    for (int i = 0; i < 32; i += 2) {
        const int rA = rbase + i * 8 + w;
        const int rB = rA + 8;
        const float4* pA = (const float4*)(zpb + (size_t)rA * D + lane * 8);
        const float4* pB = (const float4*)(zpb + (size_t)rB * D + lane * 8);
        float4 a0 = pA[0], a1 = pA[1];
        float4 b0 = pB[0], b1 = pB[1];

        float sA[NQ], sB[NQ];
#pragma unroll
        for (int s = 0; s < NQ; s++) {
            sA[s] = a0.x * q[s][0] + a0.y * q[s][1] + a0.z * q[s][2] + a0.w * q[s][3]
                  + a1.x * q[s][4] + a1.y * q[s][5] + a1.z * q[s][6] + a1.w * q[s][7];
            sB[s] = b0.x * q[s][0] + b0.y * q[s][1] + b0.z * q[s][2] + b0.w * q[s][3]
                  + b1.x * q[s][4] + b1.y * q[s][5] + b1.z * q[s][6] + b1.w * q[s][7];
        }
#pragma unroll
        for (int off = 16; off; off >>= 1) {
#pragma unroll
            for (int s = 0; s < NQ; s++) {
                sA[s] += __shfl_xor_sync(0xFFFFFFFFu, sA[s], off);
                sB[s] += __shfl_xor_sync(0xFFFFFFFFu, sB[s], off);
            }
        }
        if (lane == 0) {
#pragma unroll
            for (int s = 0; s < NQ; s++) {
                g_attn[(size_t)(b * NQ + s) * HW + rA] = sA[s];
                g_attn[(size_t)(b * NQ + s) * HW + rB] = sB[s];
            }
        }
    }
}

// ---------------------------------------------------------------------------
// Kernel B: top-10 indices per (b,q) row of 4096, descending value,
// ties -> smallest index (matches jax.lax.top_k). 96 blocks x 256 threads.
// ---------------------------------------------------------------------------
__global__ void __launch_bounds__(256) topk_kernel() {
    const int bq  = blockIdx.x;
    const int tid = threadIdx.x;

    __shared__ float sv[HW];
    __shared__ float rv[256];
    __shared__ int   ri[256];

    const float* a = g_attn + (size_t)bq * HW;
    for (int j = tid; j < HW; j += 256) sv[j] = a[j];
    __syncthreads();

    for (int k = 0; k < NPOS; k++) {
        // thread-local argmax over strided slots (j increases with s -> first
        // strict win keeps smallest index within a thread)
        float bv = -FLT_MAX; int bi = 0;
#pragma unroll
        for (int s = 0; s < HW / 256; s++) {
            int j = tid + s * 256;
            float v = sv[j];
            if (v > bv) { bv = v; bi = j; }
        }
        rv[tid] = bv; ri[tid] = bi;
        __syncthreads();
        for (int off = 128; off; off >>= 1) {
            if (tid < off) {
                float v2 = rv[tid + off]; int i2 = ri[tid + off];
                if (v2 > rv[tid] || (v2 == rv[tid] && i2 < ri[tid])) {
                    rv[tid] = v2; ri[tid] = i2;
                }
            }
            __syncthreads();
        }
        if (tid == 0) {
            g_topk[bq * NPOS + k] = ri[0];
            sv[ri[0]] = -FLT_MAX;
        }
        __syncthreads();
    }
}

// ---------------------------------------------------------------------------
// Kernel C: per-pair JSD partial sums.
// Pair index i: b = i/30, r = i%30.
//   p-row (broadcast quirk): sample_z_dis[b, r%3]   = z_dis[b, rand_idx[b, r%3]]
//   q-row:                   z_pos_dis[b, topk[b][r/10][r%10]]
// term = xlogy(p,p) + xlogy(q,q) - (p+q) * log(clip((p+q)/2, 1e-7, 1))
// ---------------------------------------------------------------------------
__global__ void __launch_bounds__(128) loss_kernel(
    const float* __restrict__ z_dis,
    const float* __restrict__ z_pos_dis,
    const void*  __restrict__ ridx)
{
    const int i   = blockIdx.x;
    const int b   = i / NPAIR;
    const int r   = i % NPAIR;
    const int qq  = r % NQ;
    const int qp  = r / NPOS;
    const int kp  = r % NPOS;
    const int tid = threadIdx.x;

    __shared__ int rows[2];
    if (tid == 0) {
        rows[0] = load_idx(ridx, b * NQ + qq);
        rows[1] = g_topk[(b * NQ + qp) * NPOS + kp];
    }
    __syncthreads();

    const float* P = z_dis     + ((size_t)b * HW + rows[0]) * NPQ;
    const float* Q = z_pos_dis + ((size_t)b * HW + rows[1]) * NPQ;

    float s = 0.f;
    for (int j = tid; j < NPQ; j += 128) {
        float p  = P[j];
        float qv = Q[j];
        float m  = logf(fminf(fmaxf(0.5f * (p + qv), 1e-7f), 1.0f));
        float t  = 0.f;
        if (p  > 0.f) t += p  * logf(p);
        if (qv > 0.f) t += qv * logf(qv);
        s += t - (p + qv) * m;
    }

    __shared__ float red[128];
    red[tid] = s;
    __syncthreads();
    for (int off = 64; off; off >>= 1) {
        if (tid < off) red[tid] += red[tid + off];
        __syncthreads();
    }
    if (tid == 0) g_part[i] = red[0];
}

// ---------------------------------------------------------------------------
// Kernel D: deterministic fixed-order final reduction and scaling.
// loss = 0.5/960 * sum(all terms)
// ---------------------------------------------------------------------------
__global__ void __launch_bounds__(256) final_kernel(float* __restrict__ out) {
    const int tid = threadIdx.x;
    float s = 0.f;
    for (int j = tid; j < B * NPAIR; j += 256) s += g_part[j];
    __shared__ float red[256];
    red[tid] = s;
    __syncthreads();
    for (int off = 128; off; off >>= 1) {
        if (tid < off) red[tid] += red[tid + off];
        __syncthreads();
    }
    if (tid == 0) out[0] = red[0] * (0.5f / (float)(B * NPAIR));
}

// ---------------------------------------------------------------------------
extern "C" void kernel_launch(void* const* d_in, const int* in_sizes, int n_in,
                              void* d_out, int out_size)
{
    (void)in_sizes; (void)n_in; (void)out_size;
    const float* z         = (const float*)d_in[0];
    const float* z_pos     = (const float*)d_in[1];
    const float* z_dis     = (const float*)d_in[2];
    const float* z_pos_dis = (const float*)d_in[3];
    const void*  ridx      = d_in[4];

    detect_idx_kernel<<<1, 32>>>((const int*)ridx);
    attn_kernel<<<dim3(B, 16), 256>>>(z, z_pos, ridx);
    topk_kernel<<<B * NQ, 256>>>();
    loss_kernel<<<B * NPAIR, 128>>>(z_dis, z_pos_dis, ridx);
    final_kernel<<<1, 256>>>((float*)d_out);
}

// round 2
// speedup vs baseline: 1.2549x; 1.2549x over previous
#include <cuda_runtime.h>
#include <math.h>
#include <float.h>

#define B     32
#define HW    4096
#define D     256
#define NPQ   512
#define NQ    3
#define NPOS  10
#define NPAIR 30          // NQ * NPOS per batch

// ---- scratch (device globals; no allocation allowed) ----
__device__ float g_attn[B * NQ * HW];       // attention scores [b][q][hw]
__device__ float g_part[B * NPAIR];         // per-pair partial loss sums

// ---------------------------------------------------------------------------
// rand_idx dtype detection, block-local (no extra kernel):
// int64 nonneg (<2^31) -> odd 32-bit words of the first 48 entries are 0.
// For int32 data that's 48 independent values in [0,4096) all being zero.
// Reads stay within 384 B (valid for both int32[96] and int64[96] layouts).
// Returns nonzero if layout is int64. Must be called by ALL threads.
// ---------------------------------------------------------------------------
__device__ __forceinline__ int detect_is64(const int* __restrict__ r32, int tid) {
    int v = (tid < 48) ? r32[2 * tid + 1] : 0;
    int any = __syncthreads_or(v != 0);
    return any == 0;
}

__device__ __forceinline__ int load_idx(const int* __restrict__ r32, int i, int is64) {
    return is64 ? r32[2 * i] : r32[i];     // little-endian low word
}

// ---------------------------------------------------------------------------
// Kernel A: attn[b][q][r] = dot(z[b, rand_idx[b,q], :], z_pos[b, r, :])
// grid (B, 16 chunks of 256 rows), 256 threads (8 warps).
// Lane owns cols [lane*8, lane*8+8); each warp does 4 rows per iteration
// (8 float4 loads in flight per lane). Packed butterfly reduction:
// rows split across lane bits 16 and 8, so 4 rows x 3 queries reduce in
// 27 shuffles instead of 60.
// ---------------------------------------------------------------------------
__global__ void __launch_bounds__(256) attn_kernel(
    const float* __restrict__ z,
    const float* __restrict__ z_pos,
    const int*  __restrict__ ridx)
{
    const int b     = blockIdx.x;
    const int chunk = blockIdx.y;
    const int tid   = threadIdx.x;
    const int w     = tid >> 5;
    const int lane  = tid & 31;

    const int is64 = detect_is64(ridx, tid);

    __shared__ int qrow[NQ];
    if (tid < NQ) qrow[tid] = load_idx(ridx, b * NQ + tid, is64);
    __syncthreads();

    // Per-lane query registers
    const float* zb = z + (size_t)b * HW * D;
    float q[NQ][8];
#pragma unroll
    for (int s = 0; s < NQ; s++) {
        const float4* qp = (const float4*)(zb + (size_t)qrow[s] * D + lane * 8);
        float4 a = qp[0], c = qp[1];
        q[s][0] = a.x; q[s][1] = a.y; q[s][2] = a.z; q[s][3] = a.w;
        q[s][4] = c.x; q[s][5] = c.y; q[s][6] = c.z; q[s][7] = c.w;
    }

    const float* zpb   = z_pos + (size_t)b * HW * D;
    const int    rbase = chunk * 256;

    for (int i = 0; i < 32; i += 4) {
        // 4 rows per warp: r = rbase + (i+u)*8 + w
        float4 a0[4], a1[4];
#pragma unroll
        for (int u = 0; u < 4; u++) {
            const int r = rbase + (i + u) * 8 + w;
            const float4* p = (const float4*)(zpb + (size_t)r * D + lane * 8);
            a0[u] = p[0];
            a1[u] = p[1];
        }

        float s[4][NQ];
#pragma unroll
        for (int u = 0; u < 4; u++) {
#pragma unroll
            for (int sq = 0; sq < NQ; sq++) {
                s[u][sq] = a0[u].x * q[sq][0] + a0[u].y * q[sq][1]
                         + a0[u].z * q[sq][2] + a0[u].w * q[sq][3]
                         + a1[u].x * q[sq][4] + a1[u].y * q[sq][5]
                         + a1[u].z * q[sq][6] + a1[u].w * q[sq][7];
            }
        }

        // Packed reduction: bit16 selects row parity {0,1}/{2,3},
        // bit8 selects row-pair. Final sums land on lanes 0,8,16,24.
        float ev[NQ];
#pragma unroll
        for (int sq = 0; sq < NQ; sq++) {
            float t0 = s[0][sq] + __shfl_xor_sync(0xFFFFFFFFu, s[0][sq], 16);
            float t1 = s[1][sq] + __shfl_xor_sync(0xFFFFFFFFu, s[1][sq], 16);
            float t2 = s[2][sq] + __shfl_xor_sync(0xFFFFFFFFu, s[2][sq], 16);
            float t3 = s[3][sq] + __shfl_xor_sync(0xFFFFFFFFu, s[3][sq], 16);
            float c0 = (lane & 16) ? t1 : t0;
            float c1 = (lane & 16) ? t3 : t2;
            float u0 = c0 + __shfl_xor_sync(0xFFFFFFFFu, c0, 8);
            float u1 = c1 + __shfl_xor_sync(0xFFFFFFFFu, c1, 8);
            float e  = (lane & 8) ? u1 : u0;
            e += __shfl_xor_sync(0xFFFFFFFFu, e, 4);
            e += __shfl_xor_sync(0xFFFFFFFFu, e, 2);
            e += __shfl_xor_sync(0xFFFFFFFFu, e, 1);
            ev[sq] = e;
        }
        if ((lane & 7) == 0) {
            // lane0->row0, lane8->row2, lane16->row1, lane24->row3
            const int rsel = ((lane >> 3) & 1) * 2 + ((lane >> 4) & 1);
            const int row  = rbase + (i + rsel) * 8 + w;
#pragma unroll
            for (int sq = 0; sq < NQ; sq++)
                g_attn[(size_t)(b * NQ + sq) * HW + row] = ev[sq];
        }
    }
}

// ---------------------------------------------------------------------------
// Kernel B (fused): per-(b,q) top-10 (descending value, ties -> smallest
// index, matching jax.lax.top_k) followed immediately by the 10 JSD pair
// partial sums that depend on this block's topk.
// Pair (within batch) r = 10*q + k:  p-row = z_dis[b, rand_idx[b, r%3]],
// q-row = z_pos_dis[b, topk[b][q][k]].
// 96 blocks x 256 threads.
// ---------------------------------------------------------------------------
__global__ void __launch_bounds__(256) topk_loss_kernel(
    const float* __restrict__ z_dis,
    const float* __restrict__ z_pos_dis,
    const int*  __restrict__ ridx)
{
    const int bq   = blockIdx.x;
    const int b    = bq / NQ;
    const int q    = bq % NQ;
    const int tid  = threadIdx.x;
    const int w    = tid >> 5;
    const int lane = tid & 31;

    __shared__ float sv[HW];
    __shared__ float wv[8];
    __shared__ int   wi[8];
    __shared__ int   sel[NPOS];
    __shared__ int   qrow[NQ];

    const int is64 = detect_is64(ridx, tid);
    if (tid < NQ) qrow[tid] = load_idx(ridx, b * NQ + tid, is64);

    const float* a = g_attn + (size_t)bq * HW;
    for (int j = tid; j < HW; j += 256) sv[j] = a[j];
    __syncthreads();

    // ---- phase 1: iterative top-10 ----
    for (int k = 0; k < NPOS; k++) {
        float bv = -FLT_MAX; int bi = 0;
#pragma unroll
        for (int s = 0; s < HW / 256; s++) {
            const int j = tid + s * 256;     // ascending j: strict > keeps min idx
            const float v = sv[j];
            if (v > bv) { bv = v; bi = j; }
        }
#pragma unroll
        for (int off = 16; off; off >>= 1) {
            float v2 = __shfl_xor_sync(0xFFFFFFFFu, bv, off);
            int   i2 = __shfl_xor_sync(0xFFFFFFFFu, bi, off);
            if (v2 > bv || (v2 == bv && i2 < bi)) { bv = v2; bi = i2; }
        }
        if (lane == 0) { wv[w] = bv; wi[w] = bi; }
        __syncthreads();
        if (w == 0) {
            float cv = (lane < 8) ? wv[lane] : -FLT_MAX;
            int   ci = (lane < 8) ? wi[lane] : 0;
#pragma unroll
            for (int off = 4; off; off >>= 1) {
                float v2 = __shfl_xor_sync(0xFFFFFFFFu, cv, off);
                int   i2 = __shfl_xor_sync(0xFFFFFFFFu, ci, off);
                if (v2 > cv || (v2 == cv && i2 < ci)) { cv = v2; ci = i2; }
            }
            if (lane == 0) { sel[k] = ci; sv[ci] = -FLT_MAX; }
        }
        __syncthreads();
    }

    // ---- phase 2: 10 JSD pairs, one warp per pair (warps 0,1 take two) ----
    for (int k = w; k < NPOS; k += 8) {
        const int rb   = 10 * q + k;          // pair index within batch
        const int prow = qrow[rb % NQ];
        const int qr   = sel[k];

        const float4* P = (const float4*)(z_dis     + ((size_t)b * HW + prow) * NPQ);
        const float4* Q = (const float4*)(z_pos_dis + ((size_t)b * HW + qr)   * NPQ);

        float s = 0.f;
#pragma unroll
        for (int t = 0; t < 4; t++) {
            const float4 pv = P[lane + t * 32];
            const float4 qv = Q[lane + t * 32];
            const float pp[4] = {pv.x, pv.y, pv.z, pv.w};
            const float qq[4] = {qv.x, qv.y, qv.z, qv.w};
#pragma unroll
            for (int e = 0; e < 4; e++) {
                const float p   = pp[e];
                const float qe  = qq[e];
                const float sum = p + qe;
                const float m   = __logf(fminf(fmaxf(0.5f * sum, 1e-7f), 1.0f));
                float t2 = 0.f;
                if (p  > 0.f) t2 += p  * __logf(p);
                if (qe > 0.f) t2 += qe * __logf(qe);
                s += t2 - sum * m;
            }
        }
#pragma unroll
        for (int off = 16; off; off >>= 1)
            s += __shfl_xor_sync(0xFFFFFFFFu, s, off);
        if (lane == 0) g_part[b * NPAIR + rb] = s;
    }
}

// ---------------------------------------------------------------------------
// Kernel C: deterministic fixed-order final reduction and scaling.
// loss = 0.5/960 * sum(all terms)
// ---------------------------------------------------------------------------
__global__ void __launch_bounds__(256) final_kernel(float* __restrict__ out) {
    const int tid = threadIdx.x;
    float s = 0.f;
    for (int j = tid; j < B * NPAIR; j += 256) s += g_part[j];
    __shared__ float red[256];
    red[tid] = s;
    __syncthreads();
    for (int off = 128; off; off >>= 1) {
        if (tid < off) red[tid] += red[tid + off];
        __syncthreads();
    }
    if (tid == 0) out[0] = red[0] * (0.5f / (float)(B * NPAIR));
}

// ---------------------------------------------------------------------------
extern "C" void kernel_launch(void* const* d_in, const int* in_sizes, int n_in,
                              void* d_out, int out_size)
{
    (void)in_sizes; (void)n_in; (void)out_size;
    const float* z         = (const float*)d_in[0];
    const float* z_pos     = (const float*)d_in[1];
    const float* z_dis     = (const float*)d_in[2];
    const float* z_pos_dis = (const float*)d_in[3];
    const int*   ridx      = (const int*)d_in[4];

    attn_kernel<<<dim3(B, 16), 256>>>(z, z_pos, ridx);
    topk_loss_kernel<<<B * NQ, 256>>>(z_dis, z_pos_dis, ridx);
    final_kernel<<<1, 256>>>((float*)d_out);
}

// round 3
// speedup vs baseline: 1.3757x; 1.0963x over previous
#include <cuda_runtime.h>
#include <math.h>
#include <float.h>

#define B      32
#define HW     4096
#define D      256
#define NPQ    512
#define NQ     3
#define NPOS   10
#define NPAIR  30          // NQ * NPOS per batch
#define CHUNK  128         // rows per attn block
#define NCHUNK (HW / CHUNK)   // 32

// ---- scratch (device globals; no allocation allowed) ----
__device__ float g_cand_val[B * NQ * NCHUNK * NPOS];  // per-chunk top-10 values
__device__ int   g_cand_idx[B * NQ * NCHUNK * NPOS];  // per-chunk top-10 hw indices
__device__ float g_part[B * NPAIR];                   // per-pair partial loss sums

// ---------------------------------------------------------------------------
// rand_idx dtype detection, block-local: int64 nonneg (<2^31) -> odd 32-bit
// words of the first 48 entries are all 0. Reads stay within 384 B (valid for
// both int32[96] and int64[96] layouts). Must be called by ALL threads.
// ---------------------------------------------------------------------------
__device__ __forceinline__ int detect_is64(const int* __restrict__ r32, int tid) {
    int v = (tid < 48) ? r32[2 * tid + 1] : 0;
    int any = __syncthreads_or(v != 0);
    return any == 0;
}

__device__ __forceinline__ int load_idx(const int* __restrict__ r32, int i, int is64) {
    return is64 ? r32[2 * i] : r32[i];     // little-endian low word
}

// ---------------------------------------------------------------------------
// Kernel A: attn scores for a 128-row chunk + per-chunk top-10 candidates.
// grid (B, 32), 256 threads (8 warps). Lane owns cols [lane*8, lane*8+8);
// each warp does 4 rows per iteration (8 float4 loads in flight per lane),
// 16 rows total per warp. Packed butterfly reduction (27 shuffles / 4 rows).
// Phase B: warps 0..2 each extract the chunk-local top-10 for one query
// (strict >, ties -> smaller index) and write 10 (val,idx) candidates.
// ---------------------------------------------------------------------------
__global__ void __launch_bounds__(256) attn_kernel(
    const float* __restrict__ z,
    const float* __restrict__ z_pos,
    const int*  __restrict__ ridx)
{
    const int b     = blockIdx.x;
    const int chunk = blockIdx.y;
    const int tid   = threadIdx.x;
    const int w     = tid >> 5;
    const int lane  = tid & 31;

    const int is64 = detect_is64(ridx, tid);

    __shared__ int   qrow[NQ];
    __shared__ float scores[NQ][CHUNK];
    if (tid < NQ) qrow[tid] = load_idx(ridx, b * NQ + tid, is64);
    __syncthreads();

    // Per-lane query registers
    const float* zb = z + (size_t)b * HW * D;
    float q[NQ][8];
#pragma unroll
    for (int s = 0; s < NQ; s++) {
        const float4* qp = (const float4*)(zb + (size_t)qrow[s] * D + lane * 8);
        float4 a = qp[0], c = qp[1];
        q[s][0] = a.x; q[s][1] = a.y; q[s][2] = a.z; q[s][3] = a.w;
        q[s][4] = c.x; q[s][5] = c.y; q[s][6] = c.z; q[s][7] = c.w;
    }

    const float* zpb   = z_pos + (size_t)b * HW * D;
    const int    rbase = chunk * CHUNK;

    for (int i = 0; i < CHUNK / 8; i += 4) {
        // 4 rows per warp: local row = (i+u)*8 + w
        float4 a0[4], a1[4];
#pragma unroll
        for (int u = 0; u < 4; u++) {
            const int r = rbase + (i + u) * 8 + w;
            const float4* p = (const float4*)(zpb + (size_t)r * D + lane * 8);
            a0[u] = p[0];
            a1[u] = p[1];
        }

        float s[4][NQ];
#pragma unroll
        for (int u = 0; u < 4; u++) {
#pragma unroll
            for (int sq = 0; sq < NQ; sq++) {
                s[u][sq] = a0[u].x * q[sq][0] + a0[u].y * q[sq][1]
                         + a0[u].z * q[sq][2] + a0[u].w * q[sq][3]
                         + a1[u].x * q[sq][4] + a1[u].y * q[sq][5]
                         + a1[u].z * q[sq][6] + a1[u].w * q[sq][7];
            }
        }

        // Packed reduction: final sums land on lanes 0,8,16,24.
        float ev[NQ];
#pragma unroll
        for (int sq = 0; sq < NQ; sq++) {
            float t0 = s[0][sq] + __shfl_xor_sync(0xFFFFFFFFu, s[0][sq], 16);
            float t1 = s[1][sq] + __shfl_xor_sync(0xFFFFFFFFu, s[1][sq], 16);
            float t2 = s[2][sq] + __shfl_xor_sync(0xFFFFFFFFu, s[2][sq], 16);
            float t3 = s[3][sq] + __shfl_xor_sync(0xFFFFFFFFu, s[3][sq], 16);
            float c0 = (lane & 16) ? t1 : t0;
            float c1 = (lane & 16) ? t3 : t2;
            float u0 = c0 + __shfl_xor_sync(0xFFFFFFFFu, c0, 8);
            float u1 = c1 + __shfl_xor_sync(0xFFFFFFFFu, c1, 8);
            float e  = (lane & 8) ? u1 : u0;
            e += __shfl_xor_sync(0xFFFFFFFFu, e, 4);
            e += __shfl_xor_sync(0xFFFFFFFFu, e, 2);
            e += __shfl_xor_sync(0xFFFFFFFFu, e, 1);
            ev[sq] = e;
        }
        if ((lane & 7) == 0) {
            // lane0->row u=0, lane8->u=2, lane16->u=1, lane24->u=3
            const int rsel = ((lane >> 3) & 1) * 2 + ((lane >> 4) & 1);
            const int rl   = (i + rsel) * 8 + w;
#pragma unroll
            for (int sq = 0; sq < NQ; sq++)
                scores[sq][rl] = ev[sq];
        }
    }
    __syncthreads();

    // ---- Phase B: per-chunk top-10 per query (warps 0..2) ----
    if (w < NQ) {
        // lane owns local rows lane + 32*s (s=0..3); ascending s -> ascending idx
        float v[4];
        int   gi[4];
#pragma unroll
        for (int s = 0; s < 4; s++) {
            const int rl = lane + 32 * s;
            v[s]  = scores[w][rl];
            gi[s] = rbase + rl;
        }
        const int obase = ((b * NQ + w) * NCHUNK + chunk) * NPOS;
        for (int k = 0; k < NPOS; k++) {
            float bv = v[0]; int bi = gi[0];
#pragma unroll
            for (int s = 1; s < 4; s++)
                if (v[s] > bv) { bv = v[s]; bi = gi[s]; }
#pragma unroll
            for (int off = 16; off; off >>= 1) {
                float v2 = __shfl_xor_sync(0xFFFFFFFFu, bv, off);
                int   i2 = __shfl_xor_sync(0xFFFFFFFFu, bi, off);
                if (v2 > bv || (v2 == bv && i2 < bi)) { bv = v2; bi = i2; }
            }
            if (lane == 0) {
                g_cand_val[obase + k] = bv;
                g_cand_idx[obase + k] = bi;
            }
            // invalidate the winner
#pragma unroll
            for (int s = 0; s < 4; s++)
                if (gi[s] == bi) v[s] = -FLT_MAX;
        }
    }
}

// ---------------------------------------------------------------------------
// Kernel B: merge 320 candidates per (b,q) -> global top-10, then compute the
// 10 JSD pair partial sums. 96 blocks x 256 threads.
// Pair (within batch) r = 10*q + k:  p-row = z_dis[b, rand_idx[b, r%3]],
// q-row = z_pos_dis[b, topk[b][q][k]].
// ---------------------------------------------------------------------------
#define NCAND (NCHUNK * NPOS)    // 320

__global__ void __launch_bounds__(256) merge_loss_kernel(
    const float* __restrict__ z_dis,
    const float* __restrict__ z_pos_dis,
    const int*  __restrict__ ridx)
{
    const int bq   = blockIdx.x;
    const int b    = bq / NQ;
    const int q    = bq % NQ;
    const int tid  = threadIdx.x;
    const int w    = tid >> 5;
    const int lane = tid & 31;

    __shared__ float cv[NCAND];
    __shared__ int   ci[NCAND];
    __shared__ int   sel[NPOS];
    __shared__ int   qrow[NQ];

    const int is64 = detect_is64(ridx, tid);
    if (tid < NQ) qrow[tid] = load_idx(ridx, b * NQ + tid, is64);

    const int cbase = bq * NCAND;
    for (int j = tid; j < NCAND; j += 256) {
        cv[j] = g_cand_val[cbase + j];
        ci[j] = g_cand_idx[cbase + j];
    }
    __syncthreads();

    // ---- global top-10 of 320 candidates (warp 0) ----
    if (w == 0) {
        for (int k = 0; k < NPOS; k++) {
            float bv = -FLT_MAX; int bi = 0x7FFFFFFF;
#pragma unroll
            for (int s = 0; s < NCAND / 32; s++) {
                const int j = lane + s * 32;
                const float v = cv[j];
                const int   i = ci[j];
                if (v > bv || (v == bv && i < bi)) { bv = v; bi = i; }
            }
#pragma unroll
            for (int off = 16; off; off >>= 1) {
                float v2 = __shfl_xor_sync(0xFFFFFFFFu, bv, off);
                int   i2 = __shfl_xor_sync(0xFFFFFFFFu, bi, off);
                if (v2 > bv || (v2 == bv && i2 < bi)) { bv = v2; bi = i2; }
            }
            if (lane == 0) sel[k] = bi;
            // invalidate winner occurrence(s)
#pragma unroll
            for (int s = 0; s < NCAND / 32; s++) {
                const int j = lane + s * 32;
                if (ci[j] == bi) cv[j] = -FLT_MAX;
            }
            __syncwarp();
        }
    }
    __syncthreads();

    // ---- 10 JSD pairs, one warp per pair (warps 0,1 take two) ----
    for (int k = w; k < NPOS; k += 8) {
        const int rb   = 10 * q + k;          // pair index within batch
        const int prow = qrow[rb % NQ];
        const int qr   = sel[k];

        const float4* P = (const float4*)(z_dis     + ((size_t)b * HW + prow) * NPQ);
        const float4* Q = (const float4*)(z_pos_dis + ((size_t)b * HW + qr)   * NPQ);

        float s = 0.f;
#pragma unroll
        for (int t = 0; t < 4; t++) {
            const float4 pv = P[lane + t * 32];
            const float4 qv = Q[lane + t * 32];
            const float pp[4] = {pv.x, pv.y, pv.z, pv.w};
            const float qq[4] = {qv.x, qv.y, qv.z, qv.w};
#pragma unroll
            for (int e = 0; e < 4; e++) {
                const float p   = pp[e];
                const float qe  = qq[e];
                const float sum = p + qe;
                const float m   = __logf(fminf(fmaxf(0.5f * sum, 1e-7f), 1.0f));
                float t2 = 0.f;
                if (p  > 0.f) t2 += p  * __logf(p);
                if (qe > 0.f) t2 += qe * __logf(qe);
                s += t2 - sum * m;
            }
        }
#pragma unroll
        for (int off = 16; off; off >>= 1)
            s += __shfl_xor_sync(0xFFFFFFFFu, s, off);
        if (lane == 0) g_part[b * NPAIR + rb] = s;
    }
}

// ---------------------------------------------------------------------------
// Kernel C: deterministic fixed-order final reduction and scaling.
// loss = 0.5/960 * sum(all terms)
// ---------------------------------------------------------------------------
__global__ void __launch_bounds__(256) final_kernel(float* __restrict__ out) {
    const int tid = threadIdx.x;
    float s = 0.f;
    for (int j = tid; j < B * NPAIR; j += 256) s += g_part[j];
    __shared__ float red[256];
    red[tid] = s;
    __syncthreads();
    for (int off = 128; off; off >>= 1) {
        if (tid < off) red[tid] += red[tid + off];
        __syncthreads();
    }
    if (tid == 0) out[0] = red[0] * (0.5f / (float)(B * NPAIR));
}

// ---------------------------------------------------------------------------
extern "C" void kernel_launch(void* const* d_in, const int* in_sizes, int n_in,
                              void* d_out, int out_size)
{
    (void)in_sizes; (void)n_in; (void)out_size;
    const float* z         = (const float*)d_in[0];
    const float* z_pos     = (const float*)d_in[1];
    const float* z_dis     = (const float*)d_in[2];
    const float* z_pos_dis = (const float*)d_in[3];
    const int*   ridx      = (const int*)d_in[4];

    attn_kernel<<<dim3(B, NCHUNK), 256>>>(z, z_pos, ridx);
    merge_loss_kernel<<<B * NQ, 256>>>(z_dis, z_pos_dis, ridx);
    final_kernel<<<1, 256>>>((float*)d_out);
}

// round 4
// speedup vs baseline: 1.3767x; 1.0007x over previous
#include <cuda_runtime.h>
#include <math.h>
#include <float.h>

#define B      32
#define HW     4096
#define D      256
#define NPQ    512
#define NQ     3
#define NPOS   10
#define NPAIR  30             // NQ * NPOS per batch
#define CHUNK  256            // rows per attn block
#define NCHUNK (HW / CHUNK)   // 16
#define NCAND  (NCHUNK * NPOS) // 160 candidates per (b,q)

// ---- scratch (device globals; no allocation allowed) ----
__device__ float    g_cand_val[B * NQ * NCAND];
__device__ int      g_cand_idx[B * NQ * NCAND];
__device__ float    g_part[B * NPAIR];
__device__ unsigned g_done;    // zero-initialized; reset by last block each launch

// ---------------------------------------------------------------------------
// rand_idx dtype detection, block-local: int64 nonneg (<2^31) -> odd 32-bit
// words of the first 48 entries are all 0. Reads stay within 384 B (valid for
// both int32[96] and int64[96] layouts). Must be called by ALL threads.
// ---------------------------------------------------------------------------
__device__ __forceinline__ int detect_is64(const int* __restrict__ r32, int tid) {
    int v = (tid < 48) ? r32[2 * tid + 1] : 0;
    int any = __syncthreads_or(v != 0);
    return any == 0;
}

__device__ __forceinline__ int load_idx(const int* __restrict__ r32, int i, int is64) {
    return is64 ? r32[2 * i] : r32[i];     // little-endian low word
}

// ---------------------------------------------------------------------------
// Kernel A: attn scores for a 256-row chunk + per-chunk top-10 candidates.
// grid (B, 16), 256 threads (8 warps). Lane owns cols [lane*8, lane*8+8);
// each warp processes 4 rows per step, software-pipelined (next step's 8
// LDG.128 issued before the current step's shuffle-reduce chain, so the
// memory pipe never drains during reductions).
// Phase B: warps 0..2 extract the chunk-local top-10 per query.
// ---------------------------------------------------------------------------
__global__ void __launch_bounds__(256, 2) attn_kernel(
    const float* __restrict__ z,
    const float* __restrict__ z_pos,
    const int*  __restrict__ ridx)
{
    const int b     = blockIdx.x;
    const int chunk = blockIdx.y;
    const int tid   = threadIdx.x;
    const int w     = tid >> 5;
    const int lane  = tid & 31;

    const int is64 = detect_is64(ridx, tid);

    __shared__ int   qrow[NQ];
    __shared__ float scores[NQ][CHUNK];
    if (tid < NQ) qrow[tid] = load_idx(ridx, b * NQ + tid, is64);
    __syncthreads();

    // Per-lane query registers
    const float* zb = z + (size_t)b * HW * D;
    float q[NQ][8];
#pragma unroll
    for (int s = 0; s < NQ; s++) {
        const float4* qp = (const float4*)(zb + (size_t)qrow[s] * D + lane * 8);
        float4 a = qp[0], c = qp[1];
        q[s][0] = a.x; q[s][1] = a.y; q[s][2] = a.z; q[s][3] = a.w;
        q[s][4] = c.x; q[s][5] = c.y; q[s][6] = c.z; q[s][7] = c.w;
    }

    const float* zpb   = z_pos + (size_t)b * HW * D;
    const int    rbase = chunk * CHUNK;
    const int    NSTEP = CHUNK / 8 / 4;           // 8 steps of 4 rows per warp

    // double-buffered row data: buf[pp][u]
    float4 a0[2][4], a1[2][4];

#pragma unroll
    for (int u = 0; u < 4; u++) {
        const int r = rbase + u * 8 + w;
        const float4* p = (const float4*)(zpb + (size_t)r * D + lane * 8);
        a0[0][u] = p[0];
        a1[0][u] = p[1];
    }

#pragma unroll
    for (int step = 0; step < NSTEP; step++) {
        const int pp = step & 1;
        // prefetch next batch before the reduce chain
        if (step + 1 < NSTEP) {
#pragma unroll
            for (int u = 0; u < 4; u++) {
                const int r = rbase + ((step + 1) * 4 + u) * 8 + w;
                const float4* p = (const float4*)(zpb + (size_t)r * D + lane * 8);
                a0[pp ^ 1][u] = p[0];
                a1[pp ^ 1][u] = p[1];
            }
        }

        float s[4][NQ];
#pragma unroll
        for (int u = 0; u < 4; u++) {
#pragma unroll
            for (int sq = 0; sq < NQ; sq++) {
                s[u][sq] = a0[pp][u].x * q[sq][0] + a0[pp][u].y * q[sq][1]
                         + a0[pp][u].z * q[sq][2] + a0[pp][u].w * q[sq][3]
                         + a1[pp][u].x * q[sq][4] + a1[pp][u].y * q[sq][5]
                         + a1[pp][u].z * q[sq][6] + a1[pp][u].w * q[sq][7];
            }
        }

        // Packed butterfly reduction: 4 rows x 3 queries in 27 shuffles.
        // Final sums land on lanes 0,8,16,24.
        float ev[NQ];
#pragma unroll
        for (int sq = 0; sq < NQ; sq++) {
            float t0 = s[0][sq] + __shfl_xor_sync(0xFFFFFFFFu, s[0][sq], 16);
            float t1 = s[1][sq] + __shfl_xor_sync(0xFFFFFFFFu, s[1][sq], 16);
            float t2 = s[2][sq] + __shfl_xor_sync(0xFFFFFFFFu, s[2][sq], 16);
            float t3 = s[3][sq] + __shfl_xor_sync(0xFFFFFFFFu, s[3][sq], 16);
            float c0 = (lane & 16) ? t1 : t0;
            float c1 = (lane & 16) ? t3 : t2;
            float u0 = c0 + __shfl_xor_sync(0xFFFFFFFFu, c0, 8);
            float u1 = c1 + __shfl_xor_sync(0xFFFFFFFFu, c1, 8);
            float e  = (lane & 8) ? u1 : u0;
            e += __shfl_xor_sync(0xFFFFFFFFu, e, 4);
            e += __shfl_xor_sync(0xFFFFFFFFu, e, 2);
            e += __shfl_xor_sync(0xFFFFFFFFu, e, 1);
            ev[sq] = e;
        }
        if ((lane & 7) == 0) {
            // lane0->row u=0, lane8->u=2, lane16->u=1, lane24->u=3
            const int rsel = ((lane >> 3) & 1) * 2 + ((lane >> 4) & 1);
            const int rl   = (step * 4 + rsel) * 8 + w;
#pragma unroll
            for (int sq = 0; sq < NQ; sq++)
                scores[sq][rl] = ev[sq];
        }
    }
    __syncthreads();

    // ---- Phase B: per-chunk top-10 per query (warps 0..2) ----
    if (w < NQ) {
        // lane owns local rows lane + 32*s (s=0..7); ascending s -> ascending idx
        float v[8];
        int   gi[8];
#pragma unroll
        for (int s = 0; s < 8; s++) {
            const int rl = lane + 32 * s;
            v[s]  = scores[w][rl];
            gi[s] = rbase + rl;
        }
        const int obase = ((b * NQ + w) * NCHUNK + chunk) * NPOS;
        for (int k = 0; k < NPOS; k++) {
            float bv = v[0]; int bi = gi[0];
#pragma unroll
            for (int s = 1; s < 8; s++)
                if (v[s] > bv) { bv = v[s]; bi = gi[s]; }
#pragma unroll
            for (int off = 16; off; off >>= 1) {
                float v2 = __shfl_xor_sync(0xFFFFFFFFu, bv, off);
                int   i2 = __shfl_xor_sync(0xFFFFFFFFu, bi, off);
                if (v2 > bv || (v2 == bv && i2 < bi)) { bv = v2; bi = i2; }
            }
            if (lane == 0) {
                g_cand_val[obase + k] = bv;
                g_cand_idx[obase + k] = bi;
            }
#pragma unroll
            for (int s = 0; s < 8; s++)
                if (gi[s] == bi) v[s] = -FLT_MAX;
        }
    }
}

// ---------------------------------------------------------------------------
// Kernel B: merge 160 candidates per (b,q) -> global top-10, compute the 10
// JSD pair partial sums, then the LAST block reduces all 960 partials in
// fixed order (deterministic), writes the output, and resets the counter.
// 96 blocks x 256 threads.
// ---------------------------------------------------------------------------
__global__ void __launch_bounds__(256) merge_loss_kernel(
    const float* __restrict__ z_dis,
    const float* __restrict__ z_pos_dis,
    const int*  __restrict__ ridx,
    float* __restrict__ out)
{
    const int bq   = blockIdx.x;
    const int b    = bq / NQ;
    const int q    = bq % NQ;
    const int tid  = threadIdx.x;
    const int w    = tid >> 5;
    const int lane = tid & 31;

    __shared__ float cv[NCAND];
    __shared__ int   ci[NCAND];
    __shared__ int   sel[NPOS];
    __shared__ int   qrow[NQ];
    __shared__ int   s_last;

    const int is64 = detect_is64(ridx, tid);
    if (tid < NQ) qrow[tid] = load_idx(ridx, b * NQ + tid, is64);

    const int cbase = bq * NCAND;
    for (int j = tid; j < NCAND; j += 256) {
        cv[j] = g_cand_val[cbase + j];
        ci[j] = g_cand_idx[cbase + j];
    }
    __syncthreads();

    // ---- global top-10 of 160 candidates (warp 0) ----
    if (w == 0) {
        for (int k = 0; k < NPOS; k++) {
            float bv = -FLT_MAX; int bi = 0x7FFFFFFF;
#pragma unroll
            for (int s = 0; s < NCAND / 32; s++) {
                const int j = lane + s * 32;
                const float v = cv[j];
                const int   i = ci[j];
                if (v > bv || (v == bv && i < bi)) { bv = v; bi = i; }
            }
#pragma unroll
            for (int off = 16; off; off >>= 1) {
                float v2 = __shfl_xor_sync(0xFFFFFFFFu, bv, off);
                int   i2 = __shfl_xor_sync(0xFFFFFFFFu, bi, off);
                if (v2 > bv || (v2 == bv && i2 < bi)) { bv = v2; bi = i2; }
            }
            if (lane == 0) sel[k] = bi;
#pragma unroll
            for (int s = 0; s < NCAND / 32; s++) {
                const int j = lane + s * 32;
                if (ci[j] == bi) cv[j] = -FLT_MAX;
            }
            __syncwarp();
        }
    }
    __syncthreads();

    // ---- 10 JSD pairs, one warp per pair (warps 0,1 take two) ----
    for (int k = w; k < NPOS; k += 8) {
        const int rb   = 10 * q + k;          // pair index within batch
        const int prow = qrow[rb % NQ];
        const int qr   = sel[k];

        const float4* P = (const float4*)(z_dis     + ((size_t)b * HW + prow) * NPQ);
        const float4* Q = (const float4*)(z_pos_dis + ((size_t)b * HW + qr)   * NPQ);

        float s = 0.f;
#pragma unroll
        for (int t = 0; t < 4; t++) {
            const float4 pv = P[lane + t * 32];
            const float4 qv = Q[lane + t * 32];
            const float pp[4] = {pv.x, pv.y, pv.z, pv.w};
            const float qq[4] = {qv.x, qv.y, qv.z, qv.w};
#pragma unroll
            for (int e = 0; e < 4; e++) {
                const float p   = pp[e];
                const float qe  = qq[e];
                const float sum = p + qe;
                const float m   = __logf(fminf(fmaxf(0.5f * sum, 1e-7f), 1.0f));
                float t2 = 0.f;
                if (p  > 0.f) t2 += p  * __logf(p);
                if (qe > 0.f) t2 += qe * __logf(qe);
                s += t2 - sum * m;
            }
        }
#pragma unroll
        for (int off = 16; off; off >>= 1)
            s += __shfl_xor_sync(0xFFFFFFFFu, s, off);
        if (lane == 0) g_part[b * NPAIR + rb] = s;
    }

    // ---- last-block-done final reduction (deterministic fixed order) ----
    __syncthreads();
    if (tid == 0) {
        __threadfence();
        s_last = (atomicAdd(&g_done, 1u) == (unsigned)(gridDim.x - 1));
    }
    __syncthreads();
    if (s_last) {
        __threadfence();
        float s = 0.f;
        for (int j = tid; j < B * NPAIR; j += 256) s += g_part[j];
        __shared__ float red[256];
        red[tid] = s;
        __syncthreads();
        for (int off = 128; off; off >>= 1) {
            if (tid < off) red[tid] += red[tid + off];
            __syncthreads();
        }
        if (tid == 0) {
            out[0] = red[0] * (0.5f / (float)(B * NPAIR));
            g_done = 0u;                 // reset for next graph replay
        }
    }
}

// ---------------------------------------------------------------------------
extern "C" void kernel_launch(void* const* d_in, const int* in_sizes, int n_in,
                              void* d_out, int out_size)
{
    (void)in_sizes; (void)n_in; (void)out_size;
    const float* z         = (const float*)d_in[0];
    const float* z_pos     = (const float*)d_in[1];
    const float* z_dis     = (const float*)d_in[2];
    const float* z_pos_dis = (const float*)d_in[3];
    const int*   ridx      = (const int*)d_in[4];

    attn_kernel<<<dim3(B, NCHUNK), 256>>>(z, z_pos, ridx);
    merge_loss_kernel<<<B * NQ, 256>>>(z_dis, z_pos_dis, ridx, (float*)d_out);
}

// round 6
// speedup vs baseline: 1.5101x; 1.0969x over previous
#include <cuda_runtime.h>
#include <math.h>
#include <float.h>

#define B      32
#define HW     4096
#define D      256
#define NPQ    512
#define NQ     3
#define NPOS   10
#define NPAIR  30              // NQ * NPOS per batch
#define CHUNK  256             // rows per attn block
#define NCHUNK (HW / CHUNK)    // 16
#define NCAND  (NCHUNK * NPOS) // 160 candidates per (b,q)

// ---- scratch (device globals; no allocation allowed) ----
__device__ float g_cand_val[B * NQ * NCAND];
__device__ int   g_cand_idx[B * NQ * NCAND];
__device__ float g_part[B * NPAIR];

// ---------------------------------------------------------------------------
// rand_idx dtype detection, block-local: int64 nonneg (<2^31) -> odd 32-bit
// words of the first 48 entries are all 0. Reads stay within 384 B (valid for
// both int32[96] and int64[96] layouts). Must be called by ALL threads.
// ---------------------------------------------------------------------------
__device__ __forceinline__ int detect_is64(const int* __restrict__ r32, int tid) {
    int v = (tid < 48) ? r32[2 * tid + 1] : 0;
    int any = __syncthreads_or(v != 0);
    return any == 0;
}

__device__ __forceinline__ int load_idx(const int* __restrict__ r32, int i, int is64) {
    return is64 ? r32[2 * i] : r32[i];     // little-endian low word
}

// ---------------------------------------------------------------------------
// Kernel A: attn scores for a 256-row chunk + per-chunk top-10 candidates.
// grid (B, 16), 256 threads (8 warps). Lane owns cols [lane*8, lane*8+8);
// 4 rows per warp per step, software-pipelined double buffer so the next
// step's 8 LDG.128 (__ldcs, evict-first stream) issue before the shuffle
// reduction chain. Phase B: warps 0..2 extract chunk-local top-10 per query.
// ---------------------------------------------------------------------------
__global__ void __launch_bounds__(256, 2) attn_kernel(
    const float* __restrict__ z,
    const float* __restrict__ z_pos,
    const int*  __restrict__ ridx)
{
    const int b     = blockIdx.x;
    const int chunk = blockIdx.y;
    const int tid   = threadIdx.x;
    const int w     = tid >> 5;
    const int lane  = tid & 31;

    const int is64 = detect_is64(ridx, tid);

    __shared__ int   qrow[NQ];
    __shared__ float scores[NQ][CHUNK];
    if (tid < NQ) qrow[tid] = load_idx(ridx, b * NQ + tid, is64);
    __syncthreads();

    // Per-lane query registers
    const float* zb = z + (size_t)b * HW * D;
    float q[NQ][8];
#pragma unroll
    for (int s = 0; s < NQ; s++) {
        const float4* qp = (const float4*)(zb + (size_t)qrow[s] * D + lane * 8);
        float4 a = qp[0], c = qp[1];
        q[s][0] = a.x; q[s][1] = a.y; q[s][2] = a.z; q[s][3] = a.w;
        q[s][4] = c.x; q[s][5] = c.y; q[s][6] = c.z; q[s][7] = c.w;
    }

    const float* zpb   = z_pos + (size_t)b * HW * D;
    const int    rbase = chunk * CHUNK;
    const int    NSTEP = CHUNK / 8 / 4;           // 8 steps of 4 rows per warp

    float4 a0[2][4], a1[2][4];

#pragma unroll
    for (int u = 0; u < 4; u++) {
        const int r = rbase + u * 8 + w;
        const float4* p = (const float4*)(zpb + (size_t)r * D + lane * 8);
        a0[0][u] = __ldcs(p);
        a1[0][u] = __ldcs(p + 1);
    }

#pragma unroll
    for (int step = 0; step < NSTEP; step++) {
        const int pp = step & 1;
        if (step + 1 < NSTEP) {
#pragma unroll
            for (int u = 0; u < 4; u++) {
                const int r = rbase + ((step + 1) * 4 + u) * 8 + w;
                const float4* p = (const float4*)(zpb + (size_t)r * D + lane * 8);
                a0[pp ^ 1][u] = __ldcs(p);
                a1[pp ^ 1][u] = __ldcs(p + 1);
            }
        }

        float s[4][NQ];
#pragma unroll
        for (int u = 0; u < 4; u++) {
#pragma unroll
            for (int sq = 0; sq < NQ; sq++) {
                s[u][sq] = a0[pp][u].x * q[sq][0] + a0[pp][u].y * q[sq][1]
                         + a0[pp][u].z * q[sq][2] + a0[pp][u].w * q[sq][3]
                         + a1[pp][u].x * q[sq][4] + a1[pp][u].y * q[sq][5]
                         + a1[pp][u].z * q[sq][6] + a1[pp][u].w * q[sq][7];
            }
        }

        // Packed butterfly reduction: 4 rows x 3 queries in 27 shuffles.
        float ev[NQ];
#pragma unroll
        for (int sq = 0; sq < NQ; sq++) {
            float t0 = s[0][sq] + __shfl_xor_sync(0xFFFFFFFFu, s[0][sq], 16);
            float t1 = s[1][sq] + __shfl_xor_sync(0xFFFFFFFFu, s[1][sq], 16);
            float t2 = s[2][sq] + __shfl_xor_sync(0xFFFFFFFFu, s[2][sq], 16);
            float t3 = s[3][sq] + __shfl_xor_sync(0xFFFFFFFFu, s[3][sq], 16);
            float c0 = (lane & 16) ? t1 : t0;
            float c1 = (lane & 16) ? t3 : t2;
            float u0 = c0 + __shfl_xor_sync(0xFFFFFFFFu, c0, 8);
            float u1 = c1 + __shfl_xor_sync(0xFFFFFFFFu, c1, 8);
            float e  = (lane & 8) ? u1 : u0;
            e += __shfl_xor_sync(0xFFFFFFFFu, e, 4);
            e += __shfl_xor_sync(0xFFFFFFFFu, e, 2);
            e += __shfl_xor_sync(0xFFFFFFFFu, e, 1);
            ev[sq] = e;
        }
        if ((lane & 7) == 0) {
            const int rsel = ((lane >> 3) & 1) * 2 + ((lane >> 4) & 1);
            const int rl   = (step * 4 + rsel) * 8 + w;
#pragma unroll
            for (int sq = 0; sq < NQ; sq++)
                scores[sq][rl] = ev[sq];
        }
    }
    __syncthreads();

    // ---- Phase B: per-chunk top-10 per query (warps 0..2) ----
    if (w < NQ) {
        float v[8];
        int   gi[8];
#pragma unroll
        for (int s = 0; s < 8; s++) {
            const int rl = lane + 32 * s;
            v[s]  = scores[w][rl];
            gi[s] = rbase + rl;
        }
        const int obase = ((b * NQ + w) * NCHUNK + chunk) * NPOS;
        for (int k = 0; k < NPOS; k++) {
            float bv = v[0]; int bi = gi[0];
#pragma unroll
            for (int s = 1; s < 8; s++)
                if (v[s] > bv) { bv = v[s]; bi = gi[s]; }
#pragma unroll
            for (int off = 16; off; off >>= 1) {
                float v2 = __shfl_xor_sync(0xFFFFFFFFu, bv, off);
                int   i2 = __shfl_xor_sync(0xFFFFFFFFu, bi, off);
                if (v2 > bv || (v2 == bv && i2 < bi)) { bv = v2; bi = i2; }
            }
            if (lane == 0) {
                g_cand_val[obase + k] = bv;
                g_cand_idx[obase + k] = bi;
            }
#pragma unroll
            for (int s = 0; s < 8; s++)
                if (gi[s] == bi) v[s] = -FLT_MAX;
        }
    }
}

// ---------------------------------------------------------------------------
// Kernel B: per-(b,q) merge + JSD. 96 blocks x 256 threads.
//   warp 0:    register-resident top-10 merge of 160 candidates
//   warps 1-3: concurrently stream the 3 z_dis p-rows (independent of topk)
//              into smem
//   then all 8 warps: the 10 JSD pairs (p from smem, q-row from global).
// Pair rb = 10*q + k: p-row = z_dis[b, rand_idx[b, rb%3]],
//                     q-row = z_pos_dis[b, sel[k]].
// ---------------------------------------------------------------------------
__global__ void __launch_bounds__(256) merge_loss_kernel(
    const float* __restrict__ z_dis,
    const float* __restrict__ z_pos_dis,
    const int*  __restrict__ ridx)
{
    const int bq   = blockIdx.x;
    const int b    = bq / NQ;
    const int q    = bq % NQ;
    const int tid  = threadIdx.x;
    const int w    = tid >> 5;
    const int lane = tid & 31;

    __shared__ int   sel[NPOS];
    __shared__ int   qrow[NQ];
    __shared__ __align__(16) float prow_s[NQ][NPQ];   // 6 KB, 16B-aligned for float4

    const int is64 = detect_is64(ridx, tid);
    if (tid < NQ) qrow[tid] = load_idx(ridx, b * NQ + tid, is64);
    __syncthreads();

    if (w >= 1 && w <= NQ) {
        // stream p-row (w-1) into smem: 512 floats, 4 float4/lane
        const int pr = qrow[w - 1];
        const float4* src = (const float4*)(z_dis + ((size_t)b * HW + pr) * NPQ);
        float4* dst = (float4*)prow_s[w - 1];
#pragma unroll
        for (int t = 0; t < 4; t++)
            dst[lane + t * 32] = src[lane + t * 32];
    } else if (w == 0) {
        // register-resident top-10 merge of 160 candidates
        const int cbase = bq * NCAND;
        float v[5];
        int   gi[5];
#pragma unroll
        for (int s = 0; s < 5; s++) {
            const int j = cbase + lane + s * 32;
            v[s]  = g_cand_val[j];
            gi[s] = g_cand_idx[j];
        }
        for (int k = 0; k < NPOS; k++) {
            float bv = v[0]; int bi = gi[0];
#pragma unroll
            for (int s = 1; s < 5; s++)
                if (v[s] > bv || (v[s] == bv && gi[s] < bi)) { bv = v[s]; bi = gi[s]; }
#pragma unroll
            for (int off = 16; off; off >>= 1) {
                float v2 = __shfl_xor_sync(0xFFFFFFFFu, bv, off);
                int   i2 = __shfl_xor_sync(0xFFFFFFFFu, bi, off);
                if (v2 > bv || (v2 == bv && i2 < bi)) { bv = v2; bi = i2; }
            }
            if (lane == 0) sel[k] = bi;
#pragma unroll
            for (int s = 0; s < 5; s++)
                if (gi[s] == bi) v[s] = -FLT_MAX;
        }
    }
    __syncthreads();

    // ---- 10 JSD pairs, one warp per pair (warps 0,1 take two) ----
    for (int k = w; k < NPOS; k += 8) {
        const int rb  = 10 * q + k;           // pair index within batch
        const int pq_ = rb % NQ;              // which p-row
        const int qr  = sel[k];

        const float4* P = (const float4*)prow_s[pq_];
        const float4* Q = (const float4*)(z_pos_dis + ((size_t)b * HW + qr) * NPQ);

        float s = 0.f;
#pragma unroll
        for (int t = 0; t < 4; t++) {
            const float4 pv = P[lane + t * 32];
            const float4 qv = Q[lane + t * 32];
            const float pp[4] = {pv.x, pv.y, pv.z, pv.w};
            const float qq[4] = {qv.x, qv.y, qv.z, qv.w};
#pragma unroll
            for (int e = 0; e < 4; e++) {
                const float p   = pp[e];
                const float qe  = qq[e];
                const float sum = p + qe;
                const float m   = __logf(fminf(fmaxf(0.5f * sum, 1e-7f), 1.0f));
                float t2 = 0.f;
                if (p  > 0.f) t2 += p  * __logf(p);
                if (qe > 0.f) t2 += qe * __logf(qe);
                s += t2 - sum * m;
            }
        }
#pragma unroll
        for (int off = 16; off; off >>= 1)
            s += __shfl_xor_sync(0xFFFFFFFFu, s, off);
        if (lane == 0) g_part[b * NPAIR + rb] = s;
    }
}

// ---------------------------------------------------------------------------
// Kernel C: deterministic fixed-order final reduction and scaling.
// ---------------------------------------------------------------------------
__global__ void __launch_bounds__(256) final_kernel(float* __restrict__ out) {
    const int tid = threadIdx.x;
    float s = 0.f;
    for (int j = tid; j < B * NPAIR; j += 256) s += g_part[j];
    __shared__ float red[256];
    red[tid] = s;
    __syncthreads();
    for (int off = 128; off; off >>= 1) {
        if (tid < off) red[tid] += red[tid + off];
        __syncthreads();
    }
    if (tid == 0) out[0] = red[0] * (0.5f / (float)(B * NPAIR));
}

// ---------------------------------------------------------------------------
extern "C" void kernel_launch(void* const* d_in, const int* in_sizes, int n_in,
                              void* d_out, int out_size)
{
    (void)in_sizes; (void)n_in; (void)out_size;
    const float* z         = (const float*)d_in[0];
    const float* z_pos     = (const float*)d_in[1];
    const float* z_dis     = (const float*)d_in[2];
    const float* z_pos_dis = (const float*)d_in[3];
    const int*   ridx      = (const int*)d_in[4];

    attn_kernel<<<dim3(B, NCHUNK), 256>>>(z, z_pos, ridx);
    merge_loss_kernel<<<B * NQ, 256>>>(z_dis, z_pos_dis, ridx);
    final_kernel<<<1, 256>>>((float*)d_out);
}

// round 7
// speedup vs baseline: 1.5579x; 1.0316x over previous
#include <cuda_runtime.h>
#include <math.h>
#include <float.h>

#define B      32
#define HW     4096
#define D      256
#define NPQ    512
#define NQ     3
#define NPOS   10
#define NPAIR  30              // NQ * NPOS per batch
#define CHUNK  256             // rows per attn block
#define NCHUNK (HW / CHUNK)    // 16
#define NCAND  (NCHUNK * NPOS) // 160 candidates per (b,q)

// ---- scratch (device globals; no allocation allowed) ----
__device__ float g_cand_val[B * NQ * NCAND];
__device__ int   g_cand_idx[B * NQ * NCAND];
__device__ float g_part[B * NPAIR];

// ---------------------------------------------------------------------------
// rand_idx dtype detection, block-local: int64 nonneg (<2^31) -> odd 32-bit
// words of the first 48 entries are all 0. Reads stay within 384 B (valid for
// both int32[96] and int64[96] layouts). Must be called by ALL threads.
// ---------------------------------------------------------------------------
__device__ __forceinline__ int detect_is64(const int* __restrict__ r32, int tid) {
    int v = (tid < 48) ? r32[2 * tid + 1] : 0;
    int any = __syncthreads_or(v != 0);
    return any == 0;
}

__device__ __forceinline__ int load_idx(const int* __restrict__ r32, int i, int is64) {
    return is64 ? r32[2 * i] : r32[i];     // little-endian low word
}

// ---------------------------------------------------------------------------
// Kernel A: attn scores for a 256-row chunk + per-chunk top-10 candidates.
// grid (B, 16), 256 threads (8 warps). Lane owns cols [lane*8, lane*8+8);
// 4 rows per warp per step, software-pipelined double buffer so the next
// step's 8 LDG.128 (__ldcs, evict-first stream) issue before the shuffle
// reduction chain. Phase B: warps 0..2 extract chunk-local top-10 per query.
// ---------------------------------------------------------------------------
__global__ void __launch_bounds__(256, 2) attn_kernel(
    const float* __restrict__ z,
    const float* __restrict__ z_pos,
    const int*  __restrict__ ridx)
{
    const int b     = blockIdx.x;
    const int chunk = blockIdx.y;
    const int tid   = threadIdx.x;
    const int w     = tid >> 5;
    const int lane  = tid & 31;

    const int is64 = detect_is64(ridx, tid);

    __shared__ int   qrow[NQ];
    __shared__ float scores[NQ][CHUNK];
    if (tid < NQ) qrow[tid] = load_idx(ridx, b * NQ + tid, is64);
    __syncthreads();

    // Per-lane query registers
    const float* zb = z + (size_t)b * HW * D;
    float q[NQ][8];
#pragma unroll
    for (int s = 0; s < NQ; s++) {
        const float4* qp = (const float4*)(zb + (size_t)qrow[s] * D + lane * 8);
        float4 a = qp[0], c = qp[1];
        q[s][0] = a.x; q[s][1] = a.y; q[s][2] = a.z; q[s][3] = a.w;
        q[s][4] = c.x; q[s][5] = c.y; q[s][6] = c.z; q[s][7] = c.w;
    }

    const float* zpb   = z_pos + (size_t)b * HW * D;
    const int    rbase = chunk * CHUNK;
    const int    NSTEP = CHUNK / 8 / 4;           // 8 steps of 4 rows per warp

    float4 a0[2][4], a1[2][4];

#pragma unroll
    for (int u = 0; u < 4; u++) {
        const int r = rbase + u * 8 + w;
        const float4* p = (const float4*)(zpb + (size_t)r * D + lane * 8);
        a0[0][u] = __ldcs(p);
        a1[0][u] = __ldcs(p + 1);
    }

#pragma unroll
    for (int step = 0; step < NSTEP; step++) {
        const int pp = step & 1;
        if (step + 1 < NSTEP) {
#pragma unroll
            for (int u = 0; u < 4; u++) {
                const int r = rbase + ((step + 1) * 4 + u) * 8 + w;
                const float4* p = (const float4*)(zpb + (size_t)r * D + lane * 8);
                a0[pp ^ 1][u] = __ldcs(p);
                a1[pp ^ 1][u] = __ldcs(p + 1);
            }
        }

        float s[4][NQ];
#pragma unroll
        for (int u = 0; u < 4; u++) {
#pragma unroll
            for (int sq = 0; sq < NQ; sq++) {
                s[u][sq] = a0[pp][u].x * q[sq][0] + a0[pp][u].y * q[sq][1]
                         + a0[pp][u].z * q[sq][2] + a0[pp][u].w * q[sq][3]
                         + a1[pp][u].x * q[sq][4] + a1[pp][u].y * q[sq][5]
                         + a1[pp][u].z * q[sq][6] + a1[pp][u].w * q[sq][7];
            }
        }

        // Packed butterfly reduction: 4 rows x 3 queries in 27 shuffles.
        float ev[NQ];
#pragma unroll
        for (int sq = 0; sq < NQ; sq++) {
            float t0 = s[0][sq] + __shfl_xor_sync(0xFFFFFFFFu, s[0][sq], 16);
            float t1 = s[1][sq] + __shfl_xor_sync(0xFFFFFFFFu, s[1][sq], 16);
            float t2 = s[2][sq] + __shfl_xor_sync(0xFFFFFFFFu, s[2][sq], 16);
            float t3 = s[3][sq] + __shfl_xor_sync(0xFFFFFFFFu, s[3][sq], 16);
            float c0 = (lane & 16) ? t1 : t0;
            float c1 = (lane & 16) ? t3 : t2;
            float u0 = c0 + __shfl_xor_sync(0xFFFFFFFFu, c0, 8);
            float u1 = c1 + __shfl_xor_sync(0xFFFFFFFFu, c1, 8);
            float e  = (lane & 8) ? u1 : u0;
            e += __shfl_xor_sync(0xFFFFFFFFu, e, 4);
            e += __shfl_xor_sync(0xFFFFFFFFu, e, 2);
            e += __shfl_xor_sync(0xFFFFFFFFu, e, 1);
            ev[sq] = e;
        }
        if ((lane & 7) == 0) {
            const int rsel = ((lane >> 3) & 1) * 2 + ((lane >> 4) & 1);
            const int rl   = (step * 4 + rsel) * 8 + w;
#pragma unroll
            for (int sq = 0; sq < NQ; sq++)
                scores[sq][rl] = ev[sq];
        }
    }
    __syncthreads();

    // ---- Phase B: per-chunk top-10 per query (warps 0..2) ----
    if (w < NQ) {
        float v[8];
        int   gi[8];
#pragma unroll
        for (int s = 0; s < 8; s++) {
            const int rl = lane + 32 * s;
            v[s]  = scores[w][rl];
            gi[s] = rbase + rl;
        }
        const int obase = ((b * NQ + w) * NCHUNK + chunk) * NPOS;
        for (int k = 0; k < NPOS; k++) {
            float bv = v[0]; int bi = gi[0];
#pragma unroll
            for (int s = 1; s < 8; s++)
                if (v[s] > bv) { bv = v[s]; bi = gi[s]; }
#pragma unroll
            for (int off = 16; off; off >>= 1) {
                float v2 = __shfl_xor_sync(0xFFFFFFFFu, bv, off);
                int   i2 = __shfl_xor_sync(0xFFFFFFFFu, bi, off);
                if (v2 > bv || (v2 == bv && i2 < bi)) { bv = v2; bi = i2; }
            }
            if (lane == 0) {
                g_cand_val[obase + k] = bv;
                g_cand_idx[obase + k] = bi;
            }
#pragma unroll
            for (int s = 0; s < 8; s++)
                if (gi[s] == bi) v[s] = -FLT_MAX;
        }
    }
}

// ---------------------------------------------------------------------------
// Kernel B: per-(b,q) merge + JSD. 96 blocks x 256 threads.
//   warp 0:    register-resident top-10 merge of 160 candidates
//   warps 1-3: concurrently stream the 3 z_dis p-rows (independent of topk)
//              into smem
//   then all 8 warps: the 10 JSD pairs (p from smem, q-row from global).
// Pair rb = 10*q + k: p-row = z_dis[b, rand_idx[b, rb%3]],
//                     q-row = z_pos_dis[b, sel[k]].
// ---------------------------------------------------------------------------
__global__ void __launch_bounds__(256) merge_loss_kernel(
    const float* __restrict__ z_dis,
    const float* __restrict__ z_pos_dis,
    const int*  __restrict__ ridx)
{
    const int bq   = blockIdx.x;
    const int b    = bq / NQ;
    const int q    = bq % NQ;
    const int tid  = threadIdx.x;
    const int w    = tid >> 5;
    const int lane = tid & 31;

    __shared__ int   sel[NPOS];
    __shared__ int   qrow[NQ];
    __shared__ __align__(16) float prow_s[NQ][NPQ];   // 6 KB, 16B-aligned for float4

    const int is64 = detect_is64(ridx, tid);
    if (tid < NQ) qrow[tid] = load_idx(ridx, b * NQ + tid, is64);
    __syncthreads();

    if (w >= 1 && w <= NQ) {
        // stream p-row (w-1) into smem: 512 floats, 4 float4/lane
        const int pr = qrow[w - 1];
        const float4* src = (const float4*)(z_dis + ((size_t)b * HW + pr) * NPQ);
        float4* dst = (float4*)prow_s[w - 1];
#pragma unroll
        for (int t = 0; t < 4; t++)
            dst[lane + t * 32] = src[lane + t * 32];
    } else if (w == 0) {
        // register-resident top-10 merge of 160 candidates
        const int cbase = bq * NCAND;
        float v[5];
        int   gi[5];
#pragma unroll
        for (int s = 0; s < 5; s++) {
            const int j = cbase + lane + s * 32;
            v[s]  = g_cand_val[j];
            gi[s] = g_cand_idx[j];
        }
        for (int k = 0; k < NPOS; k++) {
            float bv = v[0]; int bi = gi[0];
#pragma unroll
            for (int s = 1; s < 5; s++)
                if (v[s] > bv || (v[s] == bv && gi[s] < bi)) { bv = v[s]; bi = gi[s]; }
#pragma unroll
            for (int off = 16; off; off >>= 1) {
                float v2 = __shfl_xor_sync(0xFFFFFFFFu, bv, off);
                int   i2 = __shfl_xor_sync(0xFFFFFFFFu, bi, off);
                if (v2 > bv || (v2 == bv && i2 < bi)) { bv = v2; bi = i2; }
            }
            if (lane == 0) sel[k] = bi;
#pragma unroll
            for (int s = 0; s < 5; s++)
                if (gi[s] == bi) v[s] = -FLT_MAX;
        }
    }
    __syncthreads();

    // ---- 10 JSD pairs, one warp per pair (warps 0,1 take two) ----
    for (int k = w; k < NPOS; k += 8) {
        const int rb  = 10 * q + k;           // pair index within batch
        const int pq_ = rb % NQ;              // which p-row
        const int qr  = sel[k];

        const float4* P = (const float4*)prow_s[pq_];
        const float4* Q = (const float4*)(z_pos_dis + ((size_t)b * HW + qr) * NPQ);

        float s = 0.f;
#pragma unroll
        for (int t = 0; t < 4; t++) {
            const float4 pv = P[lane + t * 32];
            const float4 qv = Q[lane + t * 32];
            const float pp[4] = {pv.x, pv.y, pv.z, pv.w};
            const float qq[4] = {qv.x, qv.y, qv.z, qv.w};
#pragma unroll
            for (int e = 0; e < 4; e++) {
                const float p   = pp[e];
                const float qe  = qq[e];
                const float sum = p + qe;
                const float m   = __logf(fminf(fmaxf(0.5f * sum, 1e-7f), 1.0f));
                float t2 = 0.f;
                if (p  > 0.f) t2 += p  * __logf(p);
                if (qe > 0.f) t2 += qe * __logf(qe);
                s += t2 - sum * m;
            }
        }
#pragma unroll
        for (int off = 16; off; off >>= 1)
            s += __shfl_xor_sync(0xFFFFFFFFu, s, off);
        if (lane == 0) g_part[b * NPAIR + rb] = s;
    }
}

// ---------------------------------------------------------------------------
// Kernel C: deterministic fixed-order final reduction and scaling.
// ---------------------------------------------------------------------------
__global__ void __launch_bounds__(256) final_kernel(float* __restrict__ out) {
    const int tid = threadIdx.x;
    float s = 0.f;
    for (int j = tid; j < B * NPAIR; j += 256) s += g_part[j];
    __shared__ float red[256];
    red[tid] = s;
    __syncthreads();
    for (int off = 128; off; off >>= 1) {
        if (tid < off) red[tid] += red[tid + off];
        __syncthreads();
    }
    if (tid == 0) out[0] = red[0] * (0.5f / (float)(B * NPAIR));
}

// ---------------------------------------------------------------------------
extern "C" void kernel_launch(void* const* d_in, const int* in_sizes, int n_in,
                              void* d_out, int out_size)
{
    (void)in_sizes; (void)n_in; (void)out_size;
    const float* z         = (const float*)d_in[0];
    const float* z_pos     = (const float*)d_in[1];
    const float* z_dis     = (const float*)d_in[2];
    const float* z_pos_dis = (const float*)d_in[3];
    const int*   ridx      = (const int*)d_in[4];

    attn_kernel<<<dim3(B, NCHUNK), 256>>>(z, z_pos, ridx);
    merge_loss_kernel<<<B * NQ, 256>>>(z_dis, z_pos_dis, ridx);
    final_kernel<<<1, 256>>>((float*)d_out);
}